// round 1
// baseline (speedup 1.0000x reference)
#include <cuda_runtime.h>
#include <cstdint>

// Problem constants (fixed by the dataset)
#define KDIM 256      // IN_DIM
#define UDIM 128      // UNITS
#define MAX_NODES 100000
#define MAX_EDGES 3200000

// ---------------- device scratch (static globals: no runtime alloc) ----------
__device__ float              g_h[(size_t)MAX_NODES * UDIM];   // 51.2 MB
__device__ int                g_cnt[MAX_NODES];
__device__ int                g_off[MAX_NODES + 1];
__device__ int                g_cur[MAX_NODES];
__device__ unsigned long long g_cv[MAX_EDGES];                 // packed (col, val)

// ============================================================================
// 1) GEMM: h = x @ kernel  (M x 256) @ (256 x 128), fp32, register tiled
//    BM=128, BN=128(=UDIM), BK=16, 256 threads, 8x8 per thread
// ============================================================================
__global__ __launch_bounds__(256) void gemm_kernel(
    const float* __restrict__ X, const float* __restrict__ W, int M)
{
    __shared__ float As[16][128];   // transposed: As[k][row]
    __shared__ float Bs[16][128];   // Bs[k][col]

    const int tid = threadIdx.x;
    const int tx  = tid % 16;       // N direction (8 cols each)
    const int ty  = tid / 16;       // M direction (8 rows each)
    const int block_row = blockIdx.x * 128;

    float c[8][8];
#pragma unroll
    for (int i = 0; i < 8; i++)
#pragma unroll
        for (int j = 0; j < 8; j++) c[i][j] = 0.0f;

    const int a_r  = tid >> 2;      // 0..63
    const int a_c4 = tid & 3;       // 0..3 (float4 index within 16 k's)
    const int b_r  = tid >> 5;      // 0..7
    const int b_c4 = tid & 31;      // 0..31 (float4 index within 128 cols)

#pragma unroll 1
    for (int kt = 0; kt < KDIM; kt += 16) {
        // ---- load A tile (128 rows x 16 k), transposed into As[k][row]
#pragma unroll
        for (int p = 0; p < 2; p++) {
            int rl = a_r + p * 64;
            int grow = block_row + rl;
            float4 v = make_float4(0.f, 0.f, 0.f, 0.f);
            if (grow < M)
                v = *(const float4*)(X + (size_t)grow * KDIM + kt + a_c4 * 4);
            As[a_c4 * 4 + 0][rl] = v.x;
            As[a_c4 * 4 + 1][rl] = v.y;
            As[a_c4 * 4 + 2][rl] = v.z;
            As[a_c4 * 4 + 3][rl] = v.w;
        }
        // ---- load B tile (16 k x 128 cols)
#pragma unroll
        for (int p = 0; p < 2; p++) {
            int rl = b_r + p * 8;
            float4 v = *(const float4*)(W + (size_t)(kt + rl) * UDIM + b_c4 * 4);
            ((float4*)&Bs[rl][0])[b_c4] = v;
        }
        __syncthreads();

#pragma unroll
        for (int kk = 0; kk < 16; kk++) {
            float4 a0 = *(const float4*)&As[kk][ty * 8];
            float4 a1 = *(const float4*)&As[kk][ty * 8 + 4];
            float4 b0 = *(const float4*)&Bs[kk][tx * 8];
            float4 b1 = *(const float4*)&Bs[kk][tx * 8 + 4];
            float a[8] = {a0.x, a0.y, a0.z, a0.w, a1.x, a1.y, a1.z, a1.w};
            float b[8] = {b0.x, b0.y, b0.z, b0.w, b1.x, b1.y, b1.z, b1.w};
#pragma unroll
            for (int i = 0; i < 8; i++)
#pragma unroll
                for (int j = 0; j < 8; j++)
                    c[i][j] = fmaf(a[i], b[j], c[i][j]);
        }
        __syncthreads();
    }

    // ---- epilogue: write h (no relu here — relu is post-aggregation)
#pragma unroll
    for (int i = 0; i < 8; i++) {
        int row = block_row + ty * 8 + i;
        if (row < M) {
            float* hp = g_h + (size_t)row * UDIM + tx * 8;
            *(float4*)(hp)     = make_float4(c[i][0], c[i][1], c[i][2], c[i][3]);
            *(float4*)(hp + 4) = make_float4(c[i][4], c[i][5], c[i][6], c[i][7]);
        }
    }
}

// ============================================================================
// 2) CSR build
// ============================================================================
__global__ void zero_cnt_kernel(int n)
{
    int i = blockIdx.x * blockDim.x + threadIdx.x;
    if (i < n) g_cnt[i] = 0;
}

__global__ void hist_kernel(const int* __restrict__ rows, int E)
{
    int i = blockIdx.x * blockDim.x + threadIdx.x;
    if (i < E) atomicAdd(&g_cnt[rows[i]], 1);
}

// Single-block scan over n counts -> g_off (inclusive at [i+1]) and g_cur (exclusive)
__global__ void scan_kernel(int n)
{
    const int NW = 32;                 // 1024 threads / 32
    __shared__ int wsum[NW];
    __shared__ int carry_s;
    const int tid  = threadIdx.x;
    const int lane = tid & 31;
    const int wid  = tid >> 5;

    if (tid == 0) carry_s = 0;
    __syncthreads();

    for (int base = 0; base < n; base += 1024) {
        int i = base + tid;
        int v = (i < n) ? g_cnt[i] : 0;

        // warp inclusive scan
        int s = v;
#pragma unroll
        for (int off = 1; off < 32; off <<= 1) {
            int t = __shfl_up_sync(0xffffffffu, s, off);
            if (lane >= off) s += t;
        }
        if (lane == 31) wsum[wid] = s;
        __syncthreads();

        if (wid == 0) {
            int w = wsum[lane];
#pragma unroll
            for (int off = 1; off < 32; off <<= 1) {
                int t = __shfl_up_sync(0xffffffffu, w, off);
                if (lane >= off) w += t;
            }
            wsum[lane] = w;            // inclusive warp-sum scan
        }
        __syncthreads();

        int carry = carry_s;
        int wp = (wid > 0) ? wsum[wid - 1] : 0;
        int incl = carry + wp + s;
        if (i < n) {
            g_off[i + 1] = incl;
            g_cur[i]     = incl - v;   // exclusive
        }
        __syncthreads();
        if (tid == 0) carry_s = carry + wsum[NW - 1];
        __syncthreads();
    }
    if (tid == 0) g_off[0] = 0;
}

__global__ void scatter_kernel(const int* __restrict__ rows,
                               const int* __restrict__ cols,
                               const float* __restrict__ vals, int E)
{
    int i = blockIdx.x * blockDim.x + threadIdx.x;
    if (i < E) {
        int r = rows[i];
        int p = atomicAdd(&g_cur[r], 1);
        unsigned long long packed =
            (unsigned long long)(unsigned)cols[i] |
            ((unsigned long long)__float_as_uint(vals[i]) << 32);
        g_cv[p] = packed;
    }
}

// ============================================================================
// 3) Segment reduce: one warp per output row, atomic-free, relu epilogue
// ============================================================================
__global__ void reduce_kernel(float* __restrict__ out, int M)
{
    int warp = (blockIdx.x * blockDim.x + threadIdx.x) >> 5;
    int lane = threadIdx.x & 31;
    if (warp >= M) return;

    int s = g_off[warp];
    int e = g_off[warp + 1];

    float4 acc = make_float4(0.f, 0.f, 0.f, 0.f);
    int i = s;
    // unroll by 2 for memory-level parallelism
    for (; i + 1 < e; i += 2) {
        unsigned long long p0 = __ldg(&g_cv[i]);
        unsigned long long p1 = __ldg(&g_cv[i + 1]);
        int col0 = (int)(unsigned)(p0 & 0xffffffffu);
        int col1 = (int)(unsigned)(p1 & 0xffffffffu);
        float v0 = __uint_as_float((unsigned)(p0 >> 32));
        float v1 = __uint_as_float((unsigned)(p1 >> 32));
        float4 h0 = ((const float4*)(g_h + (size_t)col0 * UDIM))[lane];
        float4 h1 = ((const float4*)(g_h + (size_t)col1 * UDIM))[lane];
        acc.x = fmaf(v0, h0.x, acc.x); acc.y = fmaf(v0, h0.y, acc.y);
        acc.z = fmaf(v0, h0.z, acc.z); acc.w = fmaf(v0, h0.w, acc.w);
        acc.x = fmaf(v1, h1.x, acc.x); acc.y = fmaf(v1, h1.y, acc.y);
        acc.z = fmaf(v1, h1.z, acc.z); acc.w = fmaf(v1, h1.w, acc.w);
    }
    if (i < e) {
        unsigned long long p0 = __ldg(&g_cv[i]);
        int col0 = (int)(unsigned)(p0 & 0xffffffffu);
        float v0 = __uint_as_float((unsigned)(p0 >> 32));
        float4 h0 = ((const float4*)(g_h + (size_t)col0 * UDIM))[lane];
        acc.x = fmaf(v0, h0.x, acc.x); acc.y = fmaf(v0, h0.y, acc.y);
        acc.z = fmaf(v0, h0.z, acc.z); acc.w = fmaf(v0, h0.w, acc.w);
    }

    // relu
    acc.x = fmaxf(acc.x, 0.f); acc.y = fmaxf(acc.y, 0.f);
    acc.z = fmaxf(acc.z, 0.f); acc.w = fmaxf(acc.w, 0.f);

    ((float4*)(out + (size_t)warp * UDIM))[lane] = acc;
}

// ============================================================================
// launch
// ============================================================================
extern "C" void kernel_launch(void* const* d_in, const int* in_sizes, int n_in,
                              void* d_out, int out_size)
{
    const float* x      = (const float*)d_in[0];  // [M, 256]
    const float* kernel = (const float*)d_in[1];  // [256, 128]
    const int*   arows  = (const int*)d_in[2];    // [E]
    const int*   acols  = (const int*)d_in[3];    // [E]
    const float* avals  = (const float*)d_in[4];  // [E]
    float*       out    = (float*)d_out;          // [M, 128]

    const int M = in_sizes[0] / KDIM;
    const int E = in_sizes[2];

    // 1) dense transform
    gemm_kernel<<<(M + 127) / 128, 256>>>(x, kernel, M);

    // 2) CSR build
    zero_cnt_kernel<<<(M + 255) / 256, 256>>>(M);
    hist_kernel<<<(E + 255) / 256, 256>>>(arows, E);
    scan_kernel<<<1, 1024>>>(M);
    scatter_kernel<<<(E + 255) / 256, 256>>>(arows, acols, avals, E);

    // 3) atomic-free segment reduce + relu
    int warps_per_block = 256 / 32;
    int blocks = (M + warps_per_block - 1) / warps_per_block;
    reduce_kernel<<<blocks, 256>>>(out, M);
}

// round 2
// speedup vs baseline: 1.2215x; 1.2215x over previous
#include <cuda_runtime.h>
#include <cstdint>

// Problem constants (fixed by the dataset)
#define KDIM 256      // IN_DIM
#define UDIM 128      // UNITS
#define MAX_NODES 100000
#define MAX_EDGES 3200000
#define SCAN_TILE 1024
#define MAX_SCAN_BLOCKS 1024

// ---------------- device scratch (static globals: no runtime alloc) ----------
__device__ float              g_h[(size_t)MAX_NODES * UDIM];   // 51.2 MB
__device__ int                g_cnt[MAX_NODES];
__device__ int                g_off[MAX_NODES + 1];
__device__ int                g_cur[MAX_NODES];
__device__ int                g_bsum[MAX_SCAN_BLOCKS];
__device__ unsigned long long g_cv[MAX_EDGES];                 // packed (col, val)

// ============================================================================
// 1) GEMM: h = x @ kernel  (M x 256) @ (256 x 128), fp32, register tiled
//    BM=128, BN=128(=UDIM), BK=16, 256 threads, 8x8 per thread
// ============================================================================
__global__ __launch_bounds__(256) void gemm_kernel(
    const float* __restrict__ X, const float* __restrict__ W, int M)
{
    __shared__ float As[16][128];   // transposed: As[k][row]
    __shared__ float Bs[16][128];   // Bs[k][col]

    const int tid = threadIdx.x;
    const int tx  = tid % 16;       // N direction (8 cols each)
    const int ty  = tid / 16;       // M direction (8 rows each)
    const int block_row = blockIdx.x * 128;

    float c[8][8];
#pragma unroll
    for (int i = 0; i < 8; i++)
#pragma unroll
        for (int j = 0; j < 8; j++) c[i][j] = 0.0f;

    const int a_r  = tid >> 2;      // 0..63
    const int a_c4 = tid & 3;       // 0..3 (float4 index within 16 k's)
    const int b_r  = tid >> 5;      // 0..7
    const int b_c4 = tid & 31;      // 0..31 (float4 index within 128 cols)

#pragma unroll 1
    for (int kt = 0; kt < KDIM; kt += 16) {
        // ---- load A tile (128 rows x 16 k), transposed into As[k][row]
#pragma unroll
        for (int p = 0; p < 2; p++) {
            int rl = a_r + p * 64;
            int grow = block_row + rl;
            float4 v = make_float4(0.f, 0.f, 0.f, 0.f);
            if (grow < M)
                v = *(const float4*)(X + (size_t)grow * KDIM + kt + a_c4 * 4);
            As[a_c4 * 4 + 0][rl] = v.x;
            As[a_c4 * 4 + 1][rl] = v.y;
            As[a_c4 * 4 + 2][rl] = v.z;
            As[a_c4 * 4 + 3][rl] = v.w;
        }
        // ---- load B tile (16 k x 128 cols)
#pragma unroll
        for (int p = 0; p < 2; p++) {
            int rl = b_r + p * 8;
            float4 v = *(const float4*)(W + (size_t)(kt + rl) * UDIM + b_c4 * 4);
            ((float4*)&Bs[rl][0])[b_c4] = v;
        }
        __syncthreads();

#pragma unroll
        for (int kk = 0; kk < 16; kk++) {
            float4 a0 = *(const float4*)&As[kk][ty * 8];
            float4 a1 = *(const float4*)&As[kk][ty * 8 + 4];
            float4 b0 = *(const float4*)&Bs[kk][tx * 8];
            float4 b1 = *(const float4*)&Bs[kk][tx * 8 + 4];
            float a[8] = {a0.x, a0.y, a0.z, a0.w, a1.x, a1.y, a1.z, a1.w};
            float b[8] = {b0.x, b0.y, b0.z, b0.w, b1.x, b1.y, b1.z, b1.w};
#pragma unroll
            for (int i = 0; i < 8; i++)
#pragma unroll
                for (int j = 0; j < 8; j++)
                    c[i][j] = fmaf(a[i], b[j], c[i][j]);
        }
        __syncthreads();
    }

    // ---- epilogue: write h (no relu here — relu is post-aggregation)
#pragma unroll
    for (int i = 0; i < 8; i++) {
        int row = block_row + ty * 8 + i;
        if (row < M) {
            float* hp = g_h + (size_t)row * UDIM + tx * 8;
            *(float4*)(hp)     = make_float4(c[i][0], c[i][1], c[i][2], c[i][3]);
            *(float4*)(hp + 4) = make_float4(c[i][4], c[i][5], c[i][6], c[i][7]);
        }
    }
}

// ============================================================================
// 2) CSR build
// ============================================================================
__global__ void zero_cnt_kernel(int n)
{
    int i = blockIdx.x * blockDim.x + threadIdx.x;
    if (i < n) g_cnt[i] = 0;
}

__global__ void hist_kernel(const int* __restrict__ rows, int E)
{
    int i = blockIdx.x * blockDim.x + threadIdx.x;
    if (i < E) atomicAdd(&g_cnt[rows[i]], 1);
}

// ---- Phase 1: per-block sums of g_cnt (SCAN_TILE elements per block)
__global__ __launch_bounds__(SCAN_TILE) void scan_bsum_kernel(int n)
{
    __shared__ int wsum[SCAN_TILE / 32];
    const int tid  = threadIdx.x;
    const int lane = tid & 31;
    const int wid  = tid >> 5;
    int i = blockIdx.x * SCAN_TILE + tid;
    int v = (i < n) ? g_cnt[i] : 0;

    // warp reduce
#pragma unroll
    for (int off = 16; off > 0; off >>= 1)
        v += __shfl_down_sync(0xffffffffu, v, off);
    if (lane == 0) wsum[wid] = v;
    __syncthreads();
    if (wid == 0) {
        int w = (lane < SCAN_TILE / 32) ? wsum[lane] : 0;
#pragma unroll
        for (int off = 16; off > 0; off >>= 1)
            w += __shfl_down_sync(0xffffffffu, w, off);
        if (lane == 0) g_bsum[blockIdx.x] = w;
    }
}

// ---- Phase 2: exclusive scan of block sums (single block, nb <= 1024)
__global__ __launch_bounds__(1024) void scan_bases_kernel(int nb)
{
    __shared__ int wsum[32];
    const int tid  = threadIdx.x;
    const int lane = tid & 31;
    const int wid  = tid >> 5;
    int v = (tid < nb) ? g_bsum[tid] : 0;

    int s = v;
#pragma unroll
    for (int off = 1; off < 32; off <<= 1) {
        int t = __shfl_up_sync(0xffffffffu, s, off);
        if (lane >= off) s += t;
    }
    if (lane == 31) wsum[wid] = s;
    __syncthreads();
    if (wid == 0) {
        int w = wsum[lane];
#pragma unroll
        for (int off = 1; off < 32; off <<= 1) {
            int t = __shfl_up_sync(0xffffffffu, w, off);
            if (lane >= off) w += t;
        }
        wsum[lane] = w;
    }
    __syncthreads();
    int wp = (wid > 0) ? wsum[wid - 1] : 0;
    if (tid < nb) g_bsum[tid] = wp + s - v;   // exclusive base for block tid
}

// ---- Phase 3: local scan + base add, write g_off / g_cur
__global__ __launch_bounds__(SCAN_TILE) void scan_final_kernel(int n)
{
    __shared__ int wsum[SCAN_TILE / 32];
    const int tid  = threadIdx.x;
    const int lane = tid & 31;
    const int wid  = tid >> 5;
    int i = blockIdx.x * SCAN_TILE + tid;
    int v = (i < n) ? g_cnt[i] : 0;

    int s = v;
#pragma unroll
    for (int off = 1; off < 32; off <<= 1) {
        int t = __shfl_up_sync(0xffffffffu, s, off);
        if (lane >= off) s += t;
    }
    if (lane == 31) wsum[wid] = s;
    __syncthreads();
    if (wid == 0) {
        int w = wsum[lane];
#pragma unroll
        for (int off = 1; off < 32; off <<= 1) {
            int t = __shfl_up_sync(0xffffffffu, w, off);
            if (lane >= off) w += t;
        }
        wsum[lane] = w;
    }
    __syncthreads();
    int wp = (wid > 0) ? wsum[wid - 1] : 0;
    int incl = g_bsum[blockIdx.x] + wp + s;
    if (i < n) {
        g_off[i + 1] = incl;
        g_cur[i]     = incl - v;
    }
    if (i == 0) g_off[0] = 0;
}

__global__ void scatter_kernel(const int* __restrict__ rows,
                               const int* __restrict__ cols,
                               const float* __restrict__ vals, int E)
{
    int i = blockIdx.x * blockDim.x + threadIdx.x;
    if (i < E) {
        int r = rows[i];
        int p = atomicAdd(&g_cur[r], 1);
        unsigned long long packed =
            (unsigned long long)(unsigned)cols[i] |
            ((unsigned long long)__float_as_uint(vals[i]) << 32);
        g_cv[p] = packed;
    }
}

// ============================================================================
// 3) Segment reduce: one warp per output row, atomic-free, relu epilogue
// ============================================================================
__global__ void reduce_kernel(float* __restrict__ out, int M)
{
    int warp = (blockIdx.x * blockDim.x + threadIdx.x) >> 5;
    int lane = threadIdx.x & 31;
    if (warp >= M) return;

    int s = g_off[warp];
    int e = g_off[warp + 1];

    float4 acc = make_float4(0.f, 0.f, 0.f, 0.f);
    int i = s;
    // unroll by 4 for memory-level parallelism
    for (; i + 3 < e; i += 4) {
        unsigned long long p0 = __ldg(&g_cv[i]);
        unsigned long long p1 = __ldg(&g_cv[i + 1]);
        unsigned long long p2 = __ldg(&g_cv[i + 2]);
        unsigned long long p3 = __ldg(&g_cv[i + 3]);
        int c0 = (int)(unsigned)(p0 & 0xffffffffu);
        int c1 = (int)(unsigned)(p1 & 0xffffffffu);
        int c2 = (int)(unsigned)(p2 & 0xffffffffu);
        int c3 = (int)(unsigned)(p3 & 0xffffffffu);
        float v0 = __uint_as_float((unsigned)(p0 >> 32));
        float v1 = __uint_as_float((unsigned)(p1 >> 32));
        float v2 = __uint_as_float((unsigned)(p2 >> 32));
        float v3 = __uint_as_float((unsigned)(p3 >> 32));
        float4 h0 = ((const float4*)(g_h + (size_t)c0 * UDIM))[lane];
        float4 h1 = ((const float4*)(g_h + (size_t)c1 * UDIM))[lane];
        float4 h2 = ((const float4*)(g_h + (size_t)c2 * UDIM))[lane];
        float4 h3 = ((const float4*)(g_h + (size_t)c3 * UDIM))[lane];
        acc.x = fmaf(v0, h0.x, acc.x); acc.y = fmaf(v0, h0.y, acc.y);
        acc.z = fmaf(v0, h0.z, acc.z); acc.w = fmaf(v0, h0.w, acc.w);
        acc.x = fmaf(v1, h1.x, acc.x); acc.y = fmaf(v1, h1.y, acc.y);
        acc.z = fmaf(v1, h1.z, acc.z); acc.w = fmaf(v1, h1.w, acc.w);
        acc.x = fmaf(v2, h2.x, acc.x); acc.y = fmaf(v2, h2.y, acc.y);
        acc.z = fmaf(v2, h2.z, acc.z); acc.w = fmaf(v2, h2.w, acc.w);
        acc.x = fmaf(v3, h3.x, acc.x); acc.y = fmaf(v3, h3.y, acc.y);
        acc.z = fmaf(v3, h3.z, acc.z); acc.w = fmaf(v3, h3.w, acc.w);
    }
    for (; i < e; i++) {
        unsigned long long p0 = __ldg(&g_cv[i]);
        int c0 = (int)(unsigned)(p0 & 0xffffffffu);
        float v0 = __uint_as_float((unsigned)(p0 >> 32));
        float4 h0 = ((const float4*)(g_h + (size_t)c0 * UDIM))[lane];
        acc.x = fmaf(v0, h0.x, acc.x); acc.y = fmaf(v0, h0.y, acc.y);
        acc.z = fmaf(v0, h0.z, acc.z); acc.w = fmaf(v0, h0.w, acc.w);
    }

    // relu
    acc.x = fmaxf(acc.x, 0.f); acc.y = fmaxf(acc.y, 0.f);
    acc.z = fmaxf(acc.z, 0.f); acc.w = fmaxf(acc.w, 0.f);

    ((float4*)(out + (size_t)warp * UDIM))[lane] = acc;
}

// ============================================================================
// launch
// ============================================================================
extern "C" void kernel_launch(void* const* d_in, const int* in_sizes, int n_in,
                              void* d_out, int out_size)
{
    const float* x      = (const float*)d_in[0];  // [M, 256]
    const float* kernel = (const float*)d_in[1];  // [256, 128]
    const int*   arows  = (const int*)d_in[2];    // [E]
    const int*   acols  = (const int*)d_in[3];    // [E]
    const float* avals  = (const float*)d_in[4];  // [E]
    float*       out    = (float*)d_out;          // [M, 128]

    const int M = in_sizes[0] / KDIM;
    const int E = in_sizes[2];
    const int nb = (M + SCAN_TILE - 1) / SCAN_TILE;   // 98 for M=100000

    // 1) dense transform
    gemm_kernel<<<(M + 127) / 128, 256>>>(x, kernel, M);

    // 2) CSR build
    zero_cnt_kernel<<<(M + 255) / 256, 256>>>(M);
    hist_kernel<<<(E + 255) / 256, 256>>>(arows, E);
    scan_bsum_kernel<<<nb, SCAN_TILE>>>(M);
    scan_bases_kernel<<<1, 1024>>>(nb);
    scan_final_kernel<<<nb, SCAN_TILE>>>(M);
    scatter_kernel<<<(E + 255) / 256, 256>>>(arows, acols, avals, E);

    // 3) atomic-free segment reduce + relu
    int warps_per_block = 256 / 32;
    int blocks = (M + warps_per_block - 1) / warps_per_block;
    reduce_kernel<<<blocks, 256>>>(out, M);
}

// round 3
// speedup vs baseline: 1.2256x; 1.0033x over previous
#include <cuda_runtime.h>
#include <cstdint>

// Problem constants (fixed by the dataset)
#define KDIM 256      // IN_DIM
#define UDIM 128      // UNITS
#define MAX_NODES 100000
#define MAX_EDGES 3200000
#define SCAN_TILE 1024
#define MAX_SCAN_BLOCKS 1024

// ---------------- device scratch (static globals: no runtime alloc) ----------
__device__ float              g_h[(size_t)MAX_NODES * UDIM];   // 51.2 MB
__device__ int                g_cnt[MAX_NODES];
__device__ int                g_off[MAX_NODES + 1];
__device__ int                g_cur[MAX_NODES];
__device__ int                g_bsum[MAX_SCAN_BLOCKS];
__device__ unsigned long long g_cv[MAX_EDGES];                 // packed (col, val)

// ---------------- packed f32x2 helpers (Blackwell FFMA2) --------------------
__device__ __forceinline__ unsigned long long pack2(float x, float y)
{
    unsigned long long r;
    asm("mov.b64 %0, {%1, %2};" : "=l"(r) : "f"(x), "f"(y));
    return r;
}
__device__ __forceinline__ void ffma2(unsigned long long& c,
                                      unsigned long long a,
                                      unsigned long long b)
{
    asm("fma.rn.f32x2 %0, %1, %2, %0;" : "+l"(c) : "l"(a), "l"(b));
}

// ============================================================================
// 1) GEMM: h = x @ kernel  (M x 256) @ (256 x 128), fp32, register tiled
//    BM=128, BN=128(=UDIM), BK=16, 256 threads, 8x8 per thread
//    Inner loop uses packed fma.rn.f32x2 (FFMA2): 2 FMAs / instruction
// ============================================================================
__global__ __launch_bounds__(256) void gemm_kernel(
    const float* __restrict__ X, const float* __restrict__ W, int M)
{
    __shared__ float As[16][128];   // transposed: As[k][row]
    __shared__ float Bs[16][128];   // Bs[k][col]

    const int tid = threadIdx.x;
    const int tx  = tid % 16;       // N direction (8 cols each)
    const int ty  = tid / 16;       // M direction (8 rows each)
    const int block_row = blockIdx.x * 128;

    // accumulators: 8 rows x 4 column-pairs (each ull = 2 packed f32)
    unsigned long long c2[8][4];
#pragma unroll
    for (int i = 0; i < 8; i++)
#pragma unroll
        for (int j = 0; j < 4; j++) c2[i][j] = 0ull;

    const int a_r  = tid >> 2;      // 0..63
    const int a_c4 = tid & 3;       // 0..3 (float4 index within 16 k's)
    const int b_r  = tid >> 5;      // 0..7
    const int b_c4 = tid & 31;      // 0..31 (float4 index within 128 cols)

#pragma unroll 1
    for (int kt = 0; kt < KDIM; kt += 16) {
        // ---- load A tile (128 rows x 16 k), transposed into As[k][row]
#pragma unroll
        for (int p = 0; p < 2; p++) {
            int rl = a_r + p * 64;
            int grow = block_row + rl;
            float4 v = make_float4(0.f, 0.f, 0.f, 0.f);
            if (grow < M)
                v = *(const float4*)(X + (size_t)grow * KDIM + kt + a_c4 * 4);
            As[a_c4 * 4 + 0][rl] = v.x;
            As[a_c4 * 4 + 1][rl] = v.y;
            As[a_c4 * 4 + 2][rl] = v.z;
            As[a_c4 * 4 + 3][rl] = v.w;
        }
        // ---- load B tile (16 k x 128 cols)
#pragma unroll
        for (int p = 0; p < 2; p++) {
            int rl = b_r + p * 8;
            float4 v = *(const float4*)(W + (size_t)(kt + rl) * UDIM + b_c4 * 4);
            ((float4*)&Bs[rl][0])[b_c4] = v;
        }
        __syncthreads();

#pragma unroll
        for (int kk = 0; kk < 16; kk++) {
            float4 a0 = *(const float4*)&As[kk][ty * 8];
            float4 a1 = *(const float4*)&As[kk][ty * 8 + 4];
            const float2* bp = (const float2*)&Bs[kk][tx * 8];
            unsigned long long b2[4];
#pragma unroll
            for (int j = 0; j < 4; j++) {
                float2 b = bp[j];
                b2[j] = pack2(b.x, b.y);
            }
            float a[8] = {a0.x, a0.y, a0.z, a0.w, a1.x, a1.y, a1.z, a1.w};
#pragma unroll
            for (int i = 0; i < 8; i++) {
                unsigned long long a2 = pack2(a[i], a[i]);
#pragma unroll
                for (int j = 0; j < 4; j++)
                    ffma2(c2[i][j], a2, b2[j]);
            }
        }
        __syncthreads();
    }

    // ---- epilogue: write h (no relu here — relu is post-aggregation)
#pragma unroll
    for (int i = 0; i < 8; i++) {
        int row = block_row + ty * 8 + i;
        if (row < M) {
            float* hp = g_h + (size_t)row * UDIM + tx * 8;
            union { unsigned long long u[2]; float4 f; } t0, t1;
            t0.u[0] = c2[i][0]; t0.u[1] = c2[i][1];
            t1.u[0] = c2[i][2]; t1.u[1] = c2[i][3];
            *(float4*)(hp)     = t0.f;
            *(float4*)(hp + 4) = t1.f;
        }
    }
}

// ============================================================================
// 2) CSR build
// ============================================================================
__global__ void zero_cnt_kernel(int n)
{
    int i = blockIdx.x * blockDim.x + threadIdx.x;
    if (i < n) g_cnt[i] = 0;
}

__global__ void hist_kernel(const int* __restrict__ rows, int E)
{
    int i = blockIdx.x * blockDim.x + threadIdx.x;
    if (i < E) atomicAdd(&g_cnt[rows[i]], 1);
}

// ---- Phase 1: per-block sums of g_cnt (SCAN_TILE elements per block)
__global__ __launch_bounds__(SCAN_TILE) void scan_bsum_kernel(int n)
{
    __shared__ int wsum[SCAN_TILE / 32];
    const int tid  = threadIdx.x;
    const int lane = tid & 31;
    const int wid  = tid >> 5;
    int i = blockIdx.x * SCAN_TILE + tid;
    int v = (i < n) ? g_cnt[i] : 0;

#pragma unroll
    for (int off = 16; off > 0; off >>= 1)
        v += __shfl_down_sync(0xffffffffu, v, off);
    if (lane == 0) wsum[wid] = v;
    __syncthreads();
    if (wid == 0) {
        int w = (lane < SCAN_TILE / 32) ? wsum[lane] : 0;
#pragma unroll
        for (int off = 16; off > 0; off >>= 1)
            w += __shfl_down_sync(0xffffffffu, w, off);
        if (lane == 0) g_bsum[blockIdx.x] = w;
    }
}

// ---- Phase 2: exclusive scan of block sums (single block, nb <= 1024)
__global__ __launch_bounds__(1024) void scan_bases_kernel(int nb)
{
    __shared__ int wsum[32];
    const int tid  = threadIdx.x;
    const int lane = tid & 31;
    const int wid  = tid >> 5;
    int v = (tid < nb) ? g_bsum[tid] : 0;

    int s = v;
#pragma unroll
    for (int off = 1; off < 32; off <<= 1) {
        int t = __shfl_up_sync(0xffffffffu, s, off);
        if (lane >= off) s += t;
    }
    if (lane == 31) wsum[wid] = s;
    __syncthreads();
    if (wid == 0) {
        int w = wsum[lane];
#pragma unroll
        for (int off = 1; off < 32; off <<= 1) {
            int t = __shfl_up_sync(0xffffffffu, w, off);
            if (lane >= off) w += t;
        }
        wsum[lane] = w;
    }
    __syncthreads();
    int wp = (wid > 0) ? wsum[wid - 1] : 0;
    if (tid < nb) g_bsum[tid] = wp + s - v;   // exclusive base for block tid
}

// ---- Phase 3: local scan + base add, write g_off / g_cur
__global__ __launch_bounds__(SCAN_TILE) void scan_final_kernel(int n)
{
    __shared__ int wsum[SCAN_TILE / 32];
    const int tid  = threadIdx.x;
    const int lane = tid & 31;
    const int wid  = tid >> 5;
    int i = blockIdx.x * SCAN_TILE + tid;
    int v = (i < n) ? g_cnt[i] : 0;

    int s = v;
#pragma unroll
    for (int off = 1; off < 32; off <<= 1) {
        int t = __shfl_up_sync(0xffffffffu, s, off);
        if (lane >= off) s += t;
    }
    if (lane == 31) wsum[wid] = s;
    __syncthreads();
    if (wid == 0) {
        int w = wsum[lane];
#pragma unroll
        for (int off = 1; off < 32; off <<= 1) {
            int t = __shfl_up_sync(0xffffffffu, w, off);
            if (lane >= off) w += t;
        }
        wsum[lane] = w;
    }
    __syncthreads();
    int wp = (wid > 0) ? wsum[wid - 1] : 0;
    int incl = g_bsum[blockIdx.x] + wp + s;
    if (i < n) {
        g_off[i + 1] = incl;
        g_cur[i]     = incl - v;
    }
    if (i == 0) g_off[0] = 0;
}

__global__ void scatter_kernel(const int* __restrict__ rows,
                               const int* __restrict__ cols,
                               const float* __restrict__ vals, int E)
{
    int i = blockIdx.x * blockDim.x + threadIdx.x;
    if (i < E) {
        int r = rows[i];
        int p = atomicAdd(&g_cur[r], 1);
        unsigned long long packed =
            (unsigned long long)(unsigned)cols[i] |
            ((unsigned long long)__float_as_uint(vals[i]) << 32);
        g_cv[p] = packed;
    }
}

// ============================================================================
// 3) Segment reduce: one warp per output row, atomic-free, relu epilogue
// ============================================================================
__global__ void reduce_kernel(float* __restrict__ out, int M)
{
    int warp = (blockIdx.x * blockDim.x + threadIdx.x) >> 5;
    int lane = threadIdx.x & 31;
    if (warp >= M) return;

    int s = g_off[warp];
    int e = g_off[warp + 1];

    float4 acc = make_float4(0.f, 0.f, 0.f, 0.f);
    int i = s;
    for (; i + 3 < e; i += 4) {
        unsigned long long p0 = __ldg(&g_cv[i]);
        unsigned long long p1 = __ldg(&g_cv[i + 1]);
        unsigned long long p2 = __ldg(&g_cv[i + 2]);
        unsigned long long p3 = __ldg(&g_cv[i + 3]);
        int c0 = (int)(unsigned)(p0 & 0xffffffffu);
        int c1 = (int)(unsigned)(p1 & 0xffffffffu);
        int c2 = (int)(unsigned)(p2 & 0xffffffffu);
        int c3 = (int)(unsigned)(p3 & 0xffffffffu);
        float v0 = __uint_as_float((unsigned)(p0 >> 32));
        float v1 = __uint_as_float((unsigned)(p1 >> 32));
        float v2 = __uint_as_float((unsigned)(p2 >> 32));
        float v3 = __uint_as_float((unsigned)(p3 >> 32));
        float4 h0 = ((const float4*)(g_h + (size_t)c0 * UDIM))[lane];
        float4 h1 = ((const float4*)(g_h + (size_t)c1 * UDIM))[lane];
        float4 h2 = ((const float4*)(g_h + (size_t)c2 * UDIM))[lane];
        float4 h3 = ((const float4*)(g_h + (size_t)c3 * UDIM))[lane];
        acc.x = fmaf(v0, h0.x, acc.x); acc.y = fmaf(v0, h0.y, acc.y);
        acc.z = fmaf(v0, h0.z, acc.z); acc.w = fmaf(v0, h0.w, acc.w);
        acc.x = fmaf(v1, h1.x, acc.x); acc.y = fmaf(v1, h1.y, acc.y);
        acc.z = fmaf(v1, h1.z, acc.z); acc.w = fmaf(v1, h1.w, acc.w);
        acc.x = fmaf(v2, h2.x, acc.x); acc.y = fmaf(v2, h2.y, acc.y);
        acc.z = fmaf(v2, h2.z, acc.z); acc.w = fmaf(v2, h2.w, acc.w);
        acc.x = fmaf(v3, h3.x, acc.x); acc.y = fmaf(v3, h3.y, acc.y);
        acc.z = fmaf(v3, h3.z, acc.z); acc.w = fmaf(v3, h3.w, acc.w);
    }
    for (; i < e; i++) {
        unsigned long long p0 = __ldg(&g_cv[i]);
        int c0 = (int)(unsigned)(p0 & 0xffffffffu);
        float v0 = __uint_as_float((unsigned)(p0 >> 32));
        float4 h0 = ((const float4*)(g_h + (size_t)c0 * UDIM))[lane];
        acc.x = fmaf(v0, h0.x, acc.x); acc.y = fmaf(v0, h0.y, acc.y);
        acc.z = fmaf(v0, h0.z, acc.z); acc.w = fmaf(v0, h0.w, acc.w);
    }

    // relu
    acc.x = fmaxf(acc.x, 0.f); acc.y = fmaxf(acc.y, 0.f);
    acc.z = fmaxf(acc.z, 0.f); acc.w = fmaxf(acc.w, 0.f);

    ((float4*)(out + (size_t)warp * UDIM))[lane] = acc;
}

// ============================================================================
// launch
// ============================================================================
extern "C" void kernel_launch(void* const* d_in, const int* in_sizes, int n_in,
                              void* d_out, int out_size)
{
    const float* x      = (const float*)d_in[0];  // [M, 256]
    const float* kernel = (const float*)d_in[1];  // [256, 128]
    const int*   arows  = (const int*)d_in[2];    // [E]
    const int*   acols  = (const int*)d_in[3];    // [E]
    const float* avals  = (const float*)d_in[4];  // [E]
    float*       out    = (float*)d_out;          // [M, 128]

    const int M = in_sizes[0] / KDIM;
    const int E = in_sizes[2];
    const int nb = (M + SCAN_TILE - 1) / SCAN_TILE;   // 98 for M=100000

    // 1) dense transform
    gemm_kernel<<<(M + 127) / 128, 256>>>(x, kernel, M);

    // 2) CSR build
    zero_cnt_kernel<<<(M + 255) / 256, 256>>>(M);
    hist_kernel<<<(E + 255) / 256, 256>>>(arows, E);
    scan_bsum_kernel<<<nb, SCAN_TILE>>>(M);
    scan_bases_kernel<<<1, 1024>>>(nb);
    scan_final_kernel<<<nb, SCAN_TILE>>>(M);
    scatter_kernel<<<(E + 255) / 256, 256>>>(arows, acols, avals, E);

    // 3) atomic-free segment reduce + relu
    int warps_per_block = 256 / 32;
    int blocks = (M + warps_per_block - 1) / warps_per_block;
    reduce_kernel<<<blocks, 256>>>(out, M);
}

// round 5
// speedup vs baseline: 1.4220x; 1.1602x over previous
#include <cuda_runtime.h>
#include <cuda_bf16.h>
#include <cstdint>

// Problem constants (fixed by the dataset)
#define KDIM 256      // IN_DIM
#define UDIM 128      // UNITS
#define MAX_NODES 100000
#define MAX_EDGES 3200000
#define SCAN_TILE 1024
#define MAX_SCAN_BLOCKS 1024

// ---------------- device scratch (static globals: no runtime alloc) ----------
__device__ float              g_h[(size_t)MAX_NODES * UDIM];   // 51.2 MB
__device__ int                g_cnt[MAX_NODES];
__device__ int                g_off[MAX_NODES + 1];
__device__ int                g_cur[MAX_NODES];
__device__ int                g_bsum[MAX_SCAN_BLOCKS];
__device__ unsigned long long g_cv[MAX_EDGES];                 // packed (col, val)
// W split into bf16 hi/lo, transposed to K-major: [UDIM][KDIM]
__device__ __nv_bfloat16      g_bhi[UDIM * KDIM];
__device__ __nv_bfloat16      g_blo[UDIM * KDIM];

// ---------------- small helpers ----------------------------------------------
__device__ __forceinline__ uint32_t smem_u32(const void* p) {
    uint32_t a;
    asm("{ .reg .u64 t; cvta.to.shared.u64 t, %1; cvt.u32.u64 %0, t; }"
        : "=r"(a) : "l"(p));
    return a;
}

__device__ __forceinline__ void ldmatrix_x4(uint32_t& r0, uint32_t& r1,
                                            uint32_t& r2, uint32_t& r3,
                                            uint32_t addr)
{
    asm volatile("ldmatrix.sync.aligned.m8n8.x4.shared.b16 {%0,%1,%2,%3}, [%4];"
                 : "=r"(r0), "=r"(r1), "=r"(r2), "=r"(r3) : "r"(addr));
}

__device__ __forceinline__ void mma_bf16(float* d, const uint32_t* a,
                                         uint32_t b0, uint32_t b1)
{
    asm volatile(
        "mma.sync.aligned.m16n8k16.row.col.f32.bf16.bf16.f32 "
        "{%0,%1,%2,%3}, {%4,%5,%6,%7}, {%8,%9}, {%0,%1,%2,%3};"
        : "+f"(d[0]), "+f"(d[1]), "+f"(d[2]), "+f"(d[3])
        : "r"(a[0]), "r"(a[1]), "r"(a[2]), "r"(a[3]), "r"(b0), "r"(b1));
}

// ============================================================================
// 0) W prep: split + transpose W[256][128] -> g_bhi/g_blo [128][256] K-major
// ============================================================================
__global__ void wprep_kernel(const float* __restrict__ W)
{
    int i = blockIdx.x * blockDim.x + threadIdx.x;
    if (i < KDIM * UDIM) {
        int k = i / UDIM, n = i % UDIM;
        float w = W[i];
        __nv_bfloat16 hi = __float2bfloat16(w);
        float lo = w - __bfloat162float(hi);
        g_bhi[n * KDIM + k] = hi;
        g_blo[n * KDIM + k] = __float2bfloat16(lo);
    }
}

// ============================================================================
// 1) GEMM via mma.sync bf16 (3-term hi/lo split), fp32 accum
//    BM=128, BN=128, BK=32, 256 threads (8 warps), warp tile 32x64
//    smem pitch 80B -> conflict-free ldmatrix without swizzle
// ============================================================================
#define PITCH 80

__global__ __launch_bounds__(256, 1) void gemm_mma_kernel(
    const float* __restrict__ X, int M)
{
    __shared__ __align__(16) char sA_hi[128 * PITCH];
    __shared__ __align__(16) char sA_lo[128 * PITCH];
    __shared__ __align__(16) char sB_hi[128 * PITCH];
    __shared__ __align__(16) char sB_lo[128 * PITCH];

    const int tid  = threadIdx.x;
    const int wid  = tid >> 5;
    const int lane = tid & 31;
    const int warpM = wid & 3;        // 4 groups of 32 rows
    const int warpN = wid >> 2;       // 2 groups of 64 cols
    const int block_row = blockIdx.x * 128;

    float acc[2][8][4];
#pragma unroll
    for (int mg = 0; mg < 2; mg++)
#pragma unroll
        for (int ng = 0; ng < 8; ng++)
#pragma unroll
            for (int q = 0; q < 4; q++) acc[mg][ng][q] = 0.0f;

    // ldmatrix lane-address components (computed once)
    const int matIdx = lane >> 3;
    const int rowInMat = lane & 7;
    // A: row = r0 + rowInMat + (matIdx&1)*8 ; k = k0 + (matIdx>>1)*8
    const int a_roff = rowInMat + (matIdx & 1) * 8;
    const int a_koff = (matIdx >> 1) * 8;
    // B: n = n0 + (matIdx>>1)*8 + rowInMat ; k = k0 + (matIdx&1)*8
    const int b_noff = (matIdx >> 1) * 8 + rowInMat;
    const int b_koff = (matIdx & 1) * 8;

    const uint32_t sAhi = smem_u32(sA_hi);
    const uint32_t sAlo = smem_u32(sA_lo);
    const uint32_t sBhi = smem_u32(sB_hi);
    const uint32_t sBlo = smem_u32(sB_lo);

    // global->smem thread mapping
    const int ld_row  = tid >> 1;     // 0..127
    const int ld_half = tid & 1;      // 0/1 -> 16 elements each

#pragma unroll 1
    for (int kc = 0; kc < KDIM; kc += 32) {
        // ---- A: load 16 fp32, split hi/lo, store bf16
        {
            int grow = block_row + ld_row;
            float f[16];
            if (grow < M) {
                const float4* xp = (const float4*)(X + (size_t)grow * KDIM + kc + ld_half * 16);
#pragma unroll
                for (int q = 0; q < 4; q++) {
                    float4 v = xp[q];
                    f[q * 4 + 0] = v.x; f[q * 4 + 1] = v.y;
                    f[q * 4 + 2] = v.z; f[q * 4 + 3] = v.w;
                }
            } else {
#pragma unroll
                for (int q = 0; q < 16; q++) f[q] = 0.0f;
            }
            union { __nv_bfloat16 b[16]; uint4 u[2]; } hi, lo;
#pragma unroll
            for (int q = 0; q < 16; q++) {
                __nv_bfloat16 h = __float2bfloat16(f[q]);
                hi.b[q] = h;
                lo.b[q] = __float2bfloat16(f[q] - __bfloat162float(h));
            }
            char* pa = sA_hi + ld_row * PITCH + ld_half * 32;
            char* pl = sA_lo + ld_row * PITCH + ld_half * 32;
            *(uint4*)(pa)      = hi.u[0];
            *(uint4*)(pa + 16) = hi.u[1];
            *(uint4*)(pl)      = lo.u[0];
            *(uint4*)(pl + 16) = lo.u[1];
        }
        // ---- B: copy pre-split bf16 (K-major)
        {
            const uint4* bh = (const uint4*)(g_bhi + ld_row * KDIM + kc + ld_half * 16);
            const uint4* bl = (const uint4*)(g_blo + ld_row * KDIM + kc + ld_half * 16);
            char* ph = sB_hi + ld_row * PITCH + ld_half * 32;
            char* pl = sB_lo + ld_row * PITCH + ld_half * 32;
            *(uint4*)(ph)      = bh[0];
            *(uint4*)(ph + 16) = bh[1];
            *(uint4*)(pl)      = bl[0];
            *(uint4*)(pl + 16) = bl[1];
        }
        __syncthreads();

#pragma unroll
        for (int ks = 0; ks < 2; ks++) {
            const int k0 = ks * 16;
            // ---- A fragments (hi & lo), 2 m16 blocks
            uint32_t ah[2][4], al[2][4];
#pragma unroll
            for (int mg = 0; mg < 2; mg++) {
                int row = warpM * 32 + mg * 16 + a_roff;
                uint32_t off = (uint32_t)(row * PITCH + (k0 + a_koff) * 2);
                ldmatrix_x4(ah[mg][0], ah[mg][1], ah[mg][2], ah[mg][3], sAhi + off);
                ldmatrix_x4(al[mg][0], al[mg][1], al[mg][2], al[mg][3], sAlo + off);
            }
            // ---- B fragments (hi & lo), 4 n16 groups covering n64
            uint32_t bh[4][4], bl[4][4];
#pragma unroll
            for (int g = 0; g < 4; g++) {
                int n = warpN * 64 + g * 16 + b_noff;
                uint32_t off = (uint32_t)(n * PITCH + (k0 + b_koff) * 2);
                ldmatrix_x4(bh[g][0], bh[g][1], bh[g][2], bh[g][3], sBhi + off);
                ldmatrix_x4(bl[g][0], bl[g][1], bl[g][2], bl[g][3], sBlo + off);
            }
            // ---- MMAs: 3 terms x 2 mg x 8 ng
#pragma unroll
            for (int mg = 0; mg < 2; mg++) {
#pragma unroll
                for (int ng = 0; ng < 8; ng++) {
                    int g = ng >> 1, s = (ng & 1) * 2;
                    mma_bf16(acc[mg][ng], ah[mg], bh[g][s], bh[g][s + 1]); // hi*hi
                    mma_bf16(acc[mg][ng], al[mg], bh[g][s], bh[g][s + 1]); // lo*hi
                    mma_bf16(acc[mg][ng], ah[mg], bl[g][s], bl[g][s + 1]); // hi*lo
                }
            }
        }
        __syncthreads();
    }

    // ---- epilogue: write h
    const int qrow = lane >> 2;          // 0..7
    const int qcol = (lane & 3) * 2;     // 0,2,4,6
#pragma unroll
    for (int mg = 0; mg < 2; mg++) {
#pragma unroll
        for (int ng = 0; ng < 8; ng++) {
            int col = warpN * 64 + ng * 8 + qcol;
            int r0 = block_row + warpM * 32 + mg * 16 + qrow;
            if (r0 < M)
                *(float2*)(g_h + (size_t)r0 * UDIM + col) =
                    make_float2(acc[mg][ng][0], acc[mg][ng][1]);
            int r1 = r0 + 8;
            if (r1 < M)
                *(float2*)(g_h + (size_t)r1 * UDIM + col) =
                    make_float2(acc[mg][ng][2], acc[mg][ng][3]);
        }
    }
}

// ============================================================================
// 2) CSR build
// ============================================================================
__global__ void zero_cnt_kernel(int n)
{
    int i = blockIdx.x * blockDim.x + threadIdx.x;
    if (i < n) g_cnt[i] = 0;
}

__global__ void hist_kernel(const int* __restrict__ rows, int E)
{
    int i = blockIdx.x * blockDim.x + threadIdx.x;
    if (i < E) atomicAdd(&g_cnt[rows[i]], 1);
}

__global__ __launch_bounds__(SCAN_TILE) void scan_bsum_kernel(int n)
{
    __shared__ int wsum[SCAN_TILE / 32];
    const int tid  = threadIdx.x;
    const int lane = tid & 31;
    const int wid  = tid >> 5;
    int i = blockIdx.x * SCAN_TILE + tid;
    int v = (i < n) ? g_cnt[i] : 0;

#pragma unroll
    for (int off = 16; off > 0; off >>= 1)
        v += __shfl_down_sync(0xffffffffu, v, off);
    if (lane == 0) wsum[wid] = v;
    __syncthreads();
    if (wid == 0) {
        int w = (lane < SCAN_TILE / 32) ? wsum[lane] : 0;
#pragma unroll
        for (int off = 16; off > 0; off >>= 1)
            w += __shfl_down_sync(0xffffffffu, w, off);
        if (lane == 0) g_bsum[blockIdx.x] = w;
    }
}

__global__ __launch_bounds__(1024) void scan_bases_kernel(int nb)
{
    __shared__ int wsum[32];
    const int tid  = threadIdx.x;
    const int lane = tid & 31;
    const int wid  = tid >> 5;
    int v = (tid < nb) ? g_bsum[tid] : 0;

    int s = v;
#pragma unroll
    for (int off = 1; off < 32; off <<= 1) {
        int t = __shfl_up_sync(0xffffffffu, s, off);
        if (lane >= off) s += t;
    }
    if (lane == 31) wsum[wid] = s;
    __syncthreads();
    if (wid == 0) {
        int w = wsum[lane];
#pragma unroll
        for (int off = 1; off < 32; off <<= 1) {
            int t = __shfl_up_sync(0xffffffffu, w, off);
            if (lane >= off) w += t;
        }
        wsum[lane] = w;
    }
    __syncthreads();
    int wp = (wid > 0) ? wsum[wid - 1] : 0;
    if (tid < nb) g_bsum[tid] = wp + s - v;
}

__global__ __launch_bounds__(SCAN_TILE) void scan_final_kernel(int n)
{
    __shared__ int wsum[SCAN_TILE / 32];
    const int tid  = threadIdx.x;
    const int lane = tid & 31;
    const int wid  = tid >> 5;
    int i = blockIdx.x * SCAN_TILE + tid;
    int v = (i < n) ? g_cnt[i] : 0;

    int s = v;
#pragma unroll
    for (int off = 1; off < 32; off <<= 1) {
        int t = __shfl_up_sync(0xffffffffu, s, off);
        if (lane >= off) s += t;
    }
    if (lane == 31) wsum[wid] = s;
    __syncthreads();
    if (wid == 0) {
        int w = wsum[lane];
#pragma unroll
        for (int off = 1; off < 32; off <<= 1) {
            int t = __shfl_up_sync(0xffffffffu, w, off);
            if (lane >= off) w += t;
        }
        wsum[lane] = w;
    }
    __syncthreads();
    int wp = (wid > 0) ? wsum[wid - 1] : 0;
    int incl = g_bsum[blockIdx.x] + wp + s;
    if (i < n) {
        g_off[i + 1] = incl;
        g_cur[i]     = incl - v;
    }
    if (i == 0) g_off[0] = 0;
}

__global__ void scatter_kernel(const int* __restrict__ rows,
                               const int* __restrict__ cols,
                               const float* __restrict__ vals, int E)
{
    int i = blockIdx.x * blockDim.x + threadIdx.x;
    if (i < E) {
        int r = rows[i];
        int p = atomicAdd(&g_cur[r], 1);
        unsigned long long packed =
            (unsigned long long)(unsigned)cols[i] |
            ((unsigned long long)__float_as_uint(vals[i]) << 32);
        g_cv[p] = packed;
    }
}

// ============================================================================
// 3) Segment reduce: one warp per output row, atomic-free, relu epilogue
// ============================================================================
__global__ void reduce_kernel(float* __restrict__ out, int M)
{
    int warp = (blockIdx.x * blockDim.x + threadIdx.x) >> 5;
    int lane = threadIdx.x & 31;
    if (warp >= M) return;

    int s = g_off[warp];
    int e = g_off[warp + 1];

    float4 acc = make_float4(0.f, 0.f, 0.f, 0.f);
    int i = s;
    for (; i + 3 < e; i += 4) {
        unsigned long long p0 = __ldg(&g_cv[i]);
        unsigned long long p1 = __ldg(&g_cv[i + 1]);
        unsigned long long p2 = __ldg(&g_cv[i + 2]);
        unsigned long long p3 = __ldg(&g_cv[i + 3]);
        int c0 = (int)(unsigned)(p0 & 0xffffffffu);
        int c1 = (int)(unsigned)(p1 & 0xffffffffu);
        int c2 = (int)(unsigned)(p2 & 0xffffffffu);
        int c3 = (int)(unsigned)(p3 & 0xffffffffu);
        float v0 = __uint_as_float((unsigned)(p0 >> 32));
        float v1 = __uint_as_float((unsigned)(p1 >> 32));
        float v2 = __uint_as_float((unsigned)(p2 >> 32));
        float v3 = __uint_as_float((unsigned)(p3 >> 32));
        float4 h0 = ((const float4*)(g_h + (size_t)c0 * UDIM))[lane];
        float4 h1 = ((const float4*)(g_h + (size_t)c1 * UDIM))[lane];
        float4 h2 = ((const float4*)(g_h + (size_t)c2 * UDIM))[lane];
        float4 h3 = ((const float4*)(g_h + (size_t)c3 * UDIM))[lane];
        acc.x = fmaf(v0, h0.x, acc.x); acc.y = fmaf(v0, h0.y, acc.y);
        acc.z = fmaf(v0, h0.z, acc.z); acc.w = fmaf(v0, h0.w, acc.w);
        acc.x = fmaf(v1, h1.x, acc.x); acc.y = fmaf(v1, h1.y, acc.y);
        acc.z = fmaf(v1, h1.z, acc.z); acc.w = fmaf(v1, h1.w, acc.w);
        acc.x = fmaf(v2, h2.x, acc.x); acc.y = fmaf(v2, h2.y, acc.y);
        acc.z = fmaf(v2, h2.z, acc.z); acc.w = fmaf(v2, h2.w, acc.w);
        acc.x = fmaf(v3, h3.x, acc.x); acc.y = fmaf(v3, h3.y, acc.y);
        acc.z = fmaf(v3, h3.z, acc.z); acc.w = fmaf(v3, h3.w, acc.w);
    }
    for (; i < e; i++) {
        unsigned long long p0 = __ldg(&g_cv[i]);
        int c0 = (int)(unsigned)(p0 & 0xffffffffu);
        float v0 = __uint_as_float((unsigned)(p0 >> 32));
        float4 h0 = ((const float4*)(g_h + (size_t)c0 * UDIM))[lane];
        acc.x = fmaf(v0, h0.x, acc.x); acc.y = fmaf(v0, h0.y, acc.y);
        acc.z = fmaf(v0, h0.z, acc.z); acc.w = fmaf(v0, h0.w, acc.w);
    }

    acc.x = fmaxf(acc.x, 0.f); acc.y = fmaxf(acc.y, 0.f);
    acc.z = fmaxf(acc.z, 0.f); acc.w = fmaxf(acc.w, 0.f);

    ((float4*)(out + (size_t)warp * UDIM))[lane] = acc;
}

// ============================================================================
// launch
// ============================================================================
extern "C" void kernel_launch(void* const* d_in, const int* in_sizes, int n_in,
                              void* d_out, int out_size)
{
    const float* x      = (const float*)d_in[0];  // [M, 256]
    const float* kernel = (const float*)d_in[1];  // [256, 128]
    const int*   arows  = (const int*)d_in[2];    // [E]
    const int*   acols  = (const int*)d_in[3];    // [E]
    const float* avals  = (const float*)d_in[4];  // [E]
    float*       out    = (float*)d_out;          // [M, 128]

    const int M = in_sizes[0] / KDIM;
    const int E = in_sizes[2];
    const int nb = (M + SCAN_TILE - 1) / SCAN_TILE;

    // 1) dense transform via mma.sync bf16 (hi/lo 3-term split)
    wprep_kernel<<<(KDIM * UDIM + 255) / 256, 256>>>(kernel);
    gemm_mma_kernel<<<(M + 127) / 128, 256>>>(x, M);

    // 2) CSR build
    zero_cnt_kernel<<<(M + 255) / 256, 256>>>(M);
    hist_kernel<<<(E + 255) / 256, 256>>>(arows, E);
    scan_bsum_kernel<<<nb, SCAN_TILE>>>(M);
    scan_bases_kernel<<<1, 1024>>>(nb);
    scan_final_kernel<<<nb, SCAN_TILE>>>(M);
    scatter_kernel<<<(E + 255) / 256, 256>>>(arows, acols, avals, E);

    // 3) atomic-free segment reduce + relu
    int warps_per_block = 256 / 32;
    int blocks = (M + warps_per_block - 1) / warps_per_block;
    reduce_kernel<<<blocks, 256>>>(out, M);
}

// round 6
// speedup vs baseline: 1.5757x; 1.1081x over previous
#include <cuda_runtime.h>
#include <cuda_bf16.h>
#include <cuda_fp16.h>
#include <cstdint>

// Problem constants (fixed by the dataset)
#define KDIM 256      // IN_DIM
#define UDIM 128      // UNITS
#define MAX_NODES 100000
#define MAX_EDGES 3200000
#define SCAN_TILE 1024
#define MAX_SCAN_BLOCKS 1024

// ---------------- device scratch (static globals: no runtime alloc) ----------
__device__ __half             g_h[(size_t)MAX_NODES * UDIM];   // 25.6 MB (fp16)
__device__ int                g_cnt[MAX_NODES];
__device__ int                g_off[MAX_NODES + 1];
__device__ int                g_cur[MAX_NODES];
__device__ int                g_bsum[MAX_SCAN_BLOCKS];
__device__ unsigned long long g_cv[MAX_EDGES];                 // packed (col, val)
// W split into bf16 hi/lo, transposed to K-major: [UDIM][KDIM]
__device__ __nv_bfloat16      g_bhi[UDIM * KDIM];
__device__ __nv_bfloat16      g_blo[UDIM * KDIM];

// ---------------- small helpers ----------------------------------------------
__device__ __forceinline__ uint32_t smem_u32(const void* p) {
    uint32_t a;
    asm("{ .reg .u64 t; cvta.to.shared.u64 t, %1; cvt.u32.u64 %0, t; }"
        : "=r"(a) : "l"(p));
    return a;
}

__device__ __forceinline__ void ldmatrix_x4(uint32_t& r0, uint32_t& r1,
                                            uint32_t& r2, uint32_t& r3,
                                            uint32_t addr)
{
    asm volatile("ldmatrix.sync.aligned.m8n8.x4.shared.b16 {%0,%1,%2,%3}, [%4];"
                 : "=r"(r0), "=r"(r1), "=r"(r2), "=r"(r3) : "r"(addr));
}

__device__ __forceinline__ void mma_bf16(float* d, const uint32_t* a,
                                         uint32_t b0, uint32_t b1)
{
    asm volatile(
        "mma.sync.aligned.m16n8k16.row.col.f32.bf16.bf16.f32 "
        "{%0,%1,%2,%3}, {%4,%5,%6,%7}, {%8,%9}, {%0,%1,%2,%3};"
        : "+f"(d[0]), "+f"(d[1]), "+f"(d[2]), "+f"(d[3])
        : "r"(a[0]), "r"(a[1]), "r"(a[2]), "r"(a[3]), "r"(b0), "r"(b1));
}

// ============================================================================
// 0) W prep: split + transpose W[256][128] -> g_bhi/g_blo [128][256] K-major
// ============================================================================
__global__ void wprep_kernel(const float* __restrict__ W)
{
    int i = blockIdx.x * blockDim.x + threadIdx.x;
    if (i < KDIM * UDIM) {
        int k = i / UDIM, n = i % UDIM;
        float w = W[i];
        __nv_bfloat16 hi = __float2bfloat16(w);
        float lo = w - __bfloat162float(hi);
        g_bhi[n * KDIM + k] = hi;
        g_blo[n * KDIM + k] = __float2bfloat16(lo);
    }
}

// ============================================================================
// 1) GEMM via mma.sync bf16 (3-term hi/lo split), fp32 accum, fp16 h output
//    BM=128, BN=128, BK=32, 256 threads (8 warps), warp tile 32x64
//    smem pitch 80B -> conflict-free ldmatrix without swizzle
// ============================================================================
#define PITCH 80

__global__ __launch_bounds__(256, 1) void gemm_mma_kernel(
    const float* __restrict__ X, int M)
{
    __shared__ __align__(16) char sA_hi[128 * PITCH];
    __shared__ __align__(16) char sA_lo[128 * PITCH];
    __shared__ __align__(16) char sB_hi[128 * PITCH];
    __shared__ __align__(16) char sB_lo[128 * PITCH];

    const int tid  = threadIdx.x;
    const int wid  = tid >> 5;
    const int lane = tid & 31;
    const int warpM = wid & 3;        // 4 groups of 32 rows
    const int warpN = wid >> 2;       // 2 groups of 64 cols
    const int block_row = blockIdx.x * 128;

    float acc[2][8][4];
#pragma unroll
    for (int mg = 0; mg < 2; mg++)
#pragma unroll
        for (int ng = 0; ng < 8; ng++)
#pragma unroll
            for (int q = 0; q < 4; q++) acc[mg][ng][q] = 0.0f;

    const int matIdx = lane >> 3;
    const int rowInMat = lane & 7;
    const int a_roff = rowInMat + (matIdx & 1) * 8;
    const int a_koff = (matIdx >> 1) * 8;
    const int b_noff = (matIdx >> 1) * 8 + rowInMat;
    const int b_koff = (matIdx & 1) * 8;

    const uint32_t sAhi = smem_u32(sA_hi);
    const uint32_t sAlo = smem_u32(sA_lo);
    const uint32_t sBhi = smem_u32(sB_hi);
    const uint32_t sBlo = smem_u32(sB_lo);

    const int ld_row  = tid >> 1;     // 0..127
    const int ld_half = tid & 1;      // 0/1 -> 16 elements each

#pragma unroll 1
    for (int kc = 0; kc < KDIM; kc += 32) {
        // ---- A: load 16 fp32, split hi/lo, store bf16
        {
            int grow = block_row + ld_row;
            float f[16];
            if (grow < M) {
                const float4* xp = (const float4*)(X + (size_t)grow * KDIM + kc + ld_half * 16);
#pragma unroll
                for (int q = 0; q < 4; q++) {
                    float4 v = xp[q];
                    f[q * 4 + 0] = v.x; f[q * 4 + 1] = v.y;
                    f[q * 4 + 2] = v.z; f[q * 4 + 3] = v.w;
                }
            } else {
#pragma unroll
                for (int q = 0; q < 16; q++) f[q] = 0.0f;
            }
            union { __nv_bfloat16 b[16]; uint4 u[2]; } hi, lo;
#pragma unroll
            for (int q = 0; q < 16; q++) {
                __nv_bfloat16 h = __float2bfloat16(f[q]);
                hi.b[q] = h;
                lo.b[q] = __float2bfloat16(f[q] - __bfloat162float(h));
            }
            char* pa = sA_hi + ld_row * PITCH + ld_half * 32;
            char* pl = sA_lo + ld_row * PITCH + ld_half * 32;
            *(uint4*)(pa)      = hi.u[0];
            *(uint4*)(pa + 16) = hi.u[1];
            *(uint4*)(pl)      = lo.u[0];
            *(uint4*)(pl + 16) = lo.u[1];
        }
        // ---- B: copy pre-split bf16 (K-major)
        {
            const uint4* bh = (const uint4*)(g_bhi + ld_row * KDIM + kc + ld_half * 16);
            const uint4* bl = (const uint4*)(g_blo + ld_row * KDIM + kc + ld_half * 16);
            char* ph = sB_hi + ld_row * PITCH + ld_half * 32;
            char* pl = sB_lo + ld_row * PITCH + ld_half * 32;
            *(uint4*)(ph)      = bh[0];
            *(uint4*)(ph + 16) = bh[1];
            *(uint4*)(pl)      = bl[0];
            *(uint4*)(pl + 16) = bl[1];
        }
        __syncthreads();

#pragma unroll
        for (int ks = 0; ks < 2; ks++) {
            const int k0 = ks * 16;
            uint32_t ah[2][4], al[2][4];
#pragma unroll
            for (int mg = 0; mg < 2; mg++) {
                int row = warpM * 32 + mg * 16 + a_roff;
                uint32_t off = (uint32_t)(row * PITCH + (k0 + a_koff) * 2);
                ldmatrix_x4(ah[mg][0], ah[mg][1], ah[mg][2], ah[mg][3], sAhi + off);
                ldmatrix_x4(al[mg][0], al[mg][1], al[mg][2], al[mg][3], sAlo + off);
            }
            uint32_t bh[4][4], bl[4][4];
#pragma unroll
            for (int g = 0; g < 4; g++) {
                int n = warpN * 64 + g * 16 + b_noff;
                uint32_t off = (uint32_t)(n * PITCH + (k0 + b_koff) * 2);
                ldmatrix_x4(bh[g][0], bh[g][1], bh[g][2], bh[g][3], sBhi + off);
                ldmatrix_x4(bl[g][0], bl[g][1], bl[g][2], bl[g][3], sBlo + off);
            }
#pragma unroll
            for (int mg = 0; mg < 2; mg++) {
#pragma unroll
                for (int ng = 0; ng < 8; ng++) {
                    int g = ng >> 1, s = (ng & 1) * 2;
                    mma_bf16(acc[mg][ng], ah[mg], bh[g][s], bh[g][s + 1]); // hi*hi
                    mma_bf16(acc[mg][ng], al[mg], bh[g][s], bh[g][s + 1]); // lo*hi
                    mma_bf16(acc[mg][ng], ah[mg], bl[g][s], bl[g][s + 1]); // hi*lo
                }
            }
        }
        __syncthreads();
    }

    // ---- epilogue: write h as fp16
    const int qrow = lane >> 2;          // 0..7
    const int qcol = (lane & 3) * 2;     // 0,2,4,6
#pragma unroll
    for (int mg = 0; mg < 2; mg++) {
#pragma unroll
        for (int ng = 0; ng < 8; ng++) {
            int col = warpN * 64 + ng * 8 + qcol;
            int r0 = block_row + warpM * 32 + mg * 16 + qrow;
            if (r0 < M)
                *(__half2*)(g_h + (size_t)r0 * UDIM + col) =
                    __floats2half2_rn(acc[mg][ng][0], acc[mg][ng][1]);
            int r1 = r0 + 8;
            if (r1 < M)
                *(__half2*)(g_h + (size_t)r1 * UDIM + col) =
                    __floats2half2_rn(acc[mg][ng][2], acc[mg][ng][3]);
        }
    }
}

// ============================================================================
// 2) CSR build
// ============================================================================
__global__ void zero_cnt_kernel(int n)
{
    int i = blockIdx.x * blockDim.x + threadIdx.x;
    if (i < n) g_cnt[i] = 0;
}

__global__ void hist_kernel(const int* __restrict__ rows, int E)
{
    int i = blockIdx.x * blockDim.x + threadIdx.x;
    if (i < E) atomicAdd(&g_cnt[rows[i]], 1);
}

__global__ __launch_bounds__(SCAN_TILE) void scan_bsum_kernel(int n)
{
    __shared__ int wsum[SCAN_TILE / 32];
    const int tid  = threadIdx.x;
    const int lane = tid & 31;
    const int wid  = tid >> 5;
    int i = blockIdx.x * SCAN_TILE + tid;
    int v = (i < n) ? g_cnt[i] : 0;

#pragma unroll
    for (int off = 16; off > 0; off >>= 1)
        v += __shfl_down_sync(0xffffffffu, v, off);
    if (lane == 0) wsum[wid] = v;
    __syncthreads();
    if (wid == 0) {
        int w = (lane < SCAN_TILE / 32) ? wsum[lane] : 0;
#pragma unroll
        for (int off = 16; off > 0; off >>= 1)
            w += __shfl_down_sync(0xffffffffu, w, off);
        if (lane == 0) g_bsum[blockIdx.x] = w;
    }
}

__global__ __launch_bounds__(1024) void scan_bases_kernel(int nb)
{
    __shared__ int wsum[32];
    const int tid  = threadIdx.x;
    const int lane = tid & 31;
    const int wid  = tid >> 5;
    int v = (tid < nb) ? g_bsum[tid] : 0;

    int s = v;
#pragma unroll
    for (int off = 1; off < 32; off <<= 1) {
        int t = __shfl_up_sync(0xffffffffu, s, off);
        if (lane >= off) s += t;
    }
    if (lane == 31) wsum[wid] = s;
    __syncthreads();
    if (wid == 0) {
        int w = wsum[lane];
#pragma unroll
        for (int off = 1; off < 32; off <<= 1) {
            int t = __shfl_up_sync(0xffffffffu, w, off);
            if (lane >= off) w += t;
        }
        wsum[lane] = w;
    }
    __syncthreads();
    int wp = (wid > 0) ? wsum[wid - 1] : 0;
    if (tid < nb) g_bsum[tid] = wp + s - v;
}

__global__ __launch_bounds__(SCAN_TILE) void scan_final_kernel(int n)
{
    __shared__ int wsum[SCAN_TILE / 32];
    const int tid  = threadIdx.x;
    const int lane = tid & 31;
    const int wid  = tid >> 5;
    int i = blockIdx.x * SCAN_TILE + tid;
    int v = (i < n) ? g_cnt[i] : 0;

    int s = v;
#pragma unroll
    for (int off = 1; off < 32; off <<= 1) {
        int t = __shfl_up_sync(0xffffffffu, s, off);
        if (lane >= off) s += t;
    }
    if (lane == 31) wsum[wid] = s;
    __syncthreads();
    if (wid == 0) {
        int w = wsum[lane];
#pragma unroll
        for (int off = 1; off < 32; off <<= 1) {
            int t = __shfl_up_sync(0xffffffffu, w, off);
            if (lane >= off) w += t;
        }
        wsum[lane] = w;
    }
    __syncthreads();
    int wp = (wid > 0) ? wsum[wid - 1] : 0;
    int incl = g_bsum[blockIdx.x] + wp + s;
    if (i < n) {
        g_off[i + 1] = incl;
        g_cur[i]     = incl - v;
    }
    if (i == 0) g_off[0] = 0;
}

__global__ void scatter_kernel(const int* __restrict__ rows,
                               const int* __restrict__ cols,
                               const float* __restrict__ vals, int E)
{
    int i = blockIdx.x * blockDim.x + threadIdx.x;
    if (i < E) {
        int r = rows[i];
        int p = atomicAdd(&g_cur[r], 1);
        unsigned long long packed =
            (unsigned long long)(unsigned)cols[i] |
            ((unsigned long long)__float_as_uint(vals[i]) << 32);
        g_cv[p] = packed;
    }
}

// ============================================================================
// 3) Segment reduce: one warp per output row, fp16 h gathers, fp32 accum
// ============================================================================
__global__ void reduce_kernel(float* __restrict__ out, int M)
{
    int warp = (blockIdx.x * blockDim.x + threadIdx.x) >> 5;
    int lane = threadIdx.x & 31;
    if (warp >= M) return;

    int s = g_off[warp];
    int e = g_off[warp + 1];

    float4 acc = make_float4(0.f, 0.f, 0.f, 0.f);
    int i = s;
    for (; i + 3 < e; i += 4) {
        unsigned long long p0 = __ldg(&g_cv[i]);
        unsigned long long p1 = __ldg(&g_cv[i + 1]);
        unsigned long long p2 = __ldg(&g_cv[i + 2]);
        unsigned long long p3 = __ldg(&g_cv[i + 3]);
        int c0 = (int)(unsigned)(p0 & 0xffffffffu);
        int c1 = (int)(unsigned)(p1 & 0xffffffffu);
        int c2 = (int)(unsigned)(p2 & 0xffffffffu);
        int c3 = (int)(unsigned)(p3 & 0xffffffffu);
        float v0 = __uint_as_float((unsigned)(p0 >> 32));
        float v1 = __uint_as_float((unsigned)(p1 >> 32));
        float v2 = __uint_as_float((unsigned)(p2 >> 32));
        float v3 = __uint_as_float((unsigned)(p3 >> 32));
        uint2 u0 = ((const uint2*)(g_h + (size_t)c0 * UDIM))[lane];
        uint2 u1 = ((const uint2*)(g_h + (size_t)c1 * UDIM))[lane];
        uint2 u2 = ((const uint2*)(g_h + (size_t)c2 * UDIM))[lane];
        uint2 u3 = ((const uint2*)(g_h + (size_t)c3 * UDIM))[lane];
        float2 a0 = __half22float2(*(__half2*)&u0.x);
        float2 b0 = __half22float2(*(__half2*)&u0.y);
        float2 a1 = __half22float2(*(__half2*)&u1.x);
        float2 b1 = __half22float2(*(__half2*)&u1.y);
        float2 a2 = __half22float2(*(__half2*)&u2.x);
        float2 b2 = __half22float2(*(__half2*)&u2.y);
        float2 a3 = __half22float2(*(__half2*)&u3.x);
        float2 b3 = __half22float2(*(__half2*)&u3.y);
        acc.x = fmaf(v0, a0.x, acc.x); acc.y = fmaf(v0, a0.y, acc.y);
        acc.z = fmaf(v0, b0.x, acc.z); acc.w = fmaf(v0, b0.y, acc.w);
        acc.x = fmaf(v1, a1.x, acc.x); acc.y = fmaf(v1, a1.y, acc.y);
        acc.z = fmaf(v1, b1.x, acc.z); acc.w = fmaf(v1, b1.y, acc.w);
        acc.x = fmaf(v2, a2.x, acc.x); acc.y = fmaf(v2, a2.y, acc.y);
        acc.z = fmaf(v2, b2.x, acc.z); acc.w = fmaf(v2, b2.y, acc.w);
        acc.x = fmaf(v3, a3.x, acc.x); acc.y = fmaf(v3, a3.y, acc.y);
        acc.z = fmaf(v3, b3.x, acc.z); acc.w = fmaf(v3, b3.y, acc.w);
    }
    for (; i < e; i++) {
        unsigned long long p0 = __ldg(&g_cv[i]);
        int c0 = (int)(unsigned)(p0 & 0xffffffffu);
        float v0 = __uint_as_float((unsigned)(p0 >> 32));
        uint2 u0 = ((const uint2*)(g_h + (size_t)c0 * UDIM))[lane];
        float2 a0 = __half22float2(*(__half2*)&u0.x);
        float2 b0 = __half22float2(*(__half2*)&u0.y);
        acc.x = fmaf(v0, a0.x, acc.x); acc.y = fmaf(v0, a0.y, acc.y);
        acc.z = fmaf(v0, b0.x, acc.z); acc.w = fmaf(v0, b0.y, acc.w);
    }

    acc.x = fmaxf(acc.x, 0.f); acc.y = fmaxf(acc.y, 0.f);
    acc.z = fmaxf(acc.z, 0.f); acc.w = fmaxf(acc.w, 0.f);

    ((float4*)(out + (size_t)warp * UDIM))[lane] = acc;
}

// ============================================================================
// launch
// ============================================================================
extern "C" void kernel_launch(void* const* d_in, const int* in_sizes, int n_in,
                              void* d_out, int out_size)
{
    const float* x      = (const float*)d_in[0];  // [M, 256]
    const float* kernel = (const float*)d_in[1];  // [256, 128]
    const int*   arows  = (const int*)d_in[2];    // [E]
    const int*   acols  = (const int*)d_in[3];    // [E]
    const float* avals  = (const float*)d_in[4];  // [E]
    float*       out    = (float*)d_out;          // [M, 128]

    const int M = in_sizes[0] / KDIM;
    const int E = in_sizes[2];
    const int nb = (M + SCAN_TILE - 1) / SCAN_TILE;

    // 1) dense transform via mma.sync bf16 (hi/lo 3-term split)
    wprep_kernel<<<(KDIM * UDIM + 255) / 256, 256>>>(kernel);
    gemm_mma_kernel<<<(M + 127) / 128, 256>>>(x, M);

    // 2) CSR build
    zero_cnt_kernel<<<(M + 255) / 256, 256>>>(M);
    hist_kernel<<<(E + 255) / 256, 256>>>(arows, E);
    scan_bsum_kernel<<<nb, SCAN_TILE>>>(M);
    scan_bases_kernel<<<1, 1024>>>(nb);
    scan_final_kernel<<<nb, SCAN_TILE>>>(M);
    scatter_kernel<<<(E + 255) / 256, 256>>>(arows, acols, avals, E);

    // 3) atomic-free segment reduce + relu (fp16 gathers)
    int warps_per_block = 256 / 32;
    int blocks = (M + warps_per_block - 1) / warps_per_block;
    reduce_kernel<<<blocks, 256>>>(out, M);
}